// round 2
// baseline (speedup 1.0000x reference)
#include <cuda_runtime.h>
#include <math.h>

#define MBATCH 16384
#define DDIM   256
#define NELEM  (MBATCH * DDIM)

constexpr float HG = 0.005f;   // gamma / 2

constexpr int BM = 128, BN = 128, BK = 16;

enum { MODE_SP = 0, MODE_GV = 1, MODE_ZC = 2, MODE_FXZ = 3, MODE_FXV = 4 };

// ---------------- scratch (static device arrays; no runtime alloc) --------
__device__ float gSZ [NELEM];
__device__ float gBUF[NELEM];
__device__ float gV  [NELEM];
__device__ float gVH0[NELEM];
__device__ float gVH1[NELEM];
__device__ float gTMP[NELEM];
__device__ float gZ0 [NELEM];
__device__ float gZ1 [NELEM];
__device__ float gZ2 [NELEM];

// ---------------- math helpers --------------------------------------------
__device__ __forceinline__ float sp_f(float x) {
    // softplus(x) = max(x,0) + log1p(exp(-|x|))   (matches jax.nn.softplus)
    return fmaxf(x, 0.0f) + log1pf(expf(-fabsf(x)));
}

// dH_dz = G @ W^T with G = 0.5*sigma*(vh^2 - 1/s) = 0.5*expm1(-s)*(1/s - vh^2)
__device__ __forceinline__ float gfun(float s, float vh) {
    float e = expm1f(-s);
    return 0.5f * e * (1.0f / s - vh * vh);
}

__device__ __forceinline__ float4 ld4(const float* p) { return *(const float4*)p; }

// ---------------- fused GEMM kernel ----------------------------------------
// TRANSB=false: acc[r,j] = sum_k A[r,k] * W[k,j]
// TRANSB=true : acc[r,j] = sum_k A[r,k] * W[j,k]
//
// Modes:
//   SP : O1 = softplus(A@W + bias)
//   GV : O1 = 0.5*expm1(-s)/s,  s = softplus(A@W + bias)
//   ZC : A = Gv(vh);  C = A@W^T.
//        O1 = BUF = HG*(SZ*vh + 2C)          (X1=z, X2=SZ, X3=vh)
//        O2 = zn1 = z + BUF + HG*SZ*vh
//   FXZ: s = softplus(A@W + bias); O1 = X1 + X2 + HG*s*X3
//        (X1 = zn (== A), X2 = BUF, X3 = vh)
//   FXV: A generated on the fly: A = gfun(X1, X2)  (X1=SZ, X2=vh_cur)
//        acc = A@W^T;  O1 = X3 - HG*acc      (X3 = vh_cur base)
template <int MODE, bool TRANSB>
__global__ __launch_bounds__(256, 2)
void rhmc_gemm(const float* __restrict__ A, const float* __restrict__ W,
               const float* __restrict__ bias,
               const float* __restrict__ X1, const float* __restrict__ X2,
               const float* __restrict__ X3,
               float* __restrict__ O1, float* __restrict__ O2)
{
    __shared__ float As[BK][BM + 4];
    __shared__ float Bs[BK][BN + 4];

    const int row0 = blockIdx.y * BM;
    const int col0 = blockIdx.x * BN;
    const int tid  = threadIdx.x;
    const int tx   = tid & 15;
    const int ty   = tid >> 4;

    float acc[8][8];
#pragma unroll
    for (int i = 0; i < 8; i++)
#pragma unroll
        for (int j = 0; j < 8; j++) acc[i][j] = 0.0f;

    const int lm   = tid >> 2;        // 0..63
    const int lk   = (tid & 3) * 4;   // 0,4,8,12
    const int bk_r = tid >> 5;        // 0..7
    const int bj   = (tid & 31) * 4;  // 0..124

    for (int k0 = 0; k0 < DDIM; k0 += BK) {
        // ---- A tile (BM x BK), stored transposed As[k][m] ----
#pragma unroll
        for (int p = 0; p < 2; p++) {
            const int m = lm + p * 64;
            const size_t gofs = (size_t)(row0 + m) * DDIM + k0 + lk;
            float4 av;
            if (MODE == MODE_FXV) {
                float4 s4 = ld4(X1 + gofs);
                float4 v4 = ld4(X2 + gofs);
                av.x = gfun(s4.x, v4.x);
                av.y = gfun(s4.y, v4.y);
                av.z = gfun(s4.z, v4.z);
                av.w = gfun(s4.w, v4.w);
            } else {
                av = ld4(A + gofs);
            }
            As[lk + 0][m] = av.x;
            As[lk + 1][m] = av.y;
            As[lk + 2][m] = av.z;
            As[lk + 3][m] = av.w;
        }
        // ---- B tile (BK x BN) ----
        if (!TRANSB) {
#pragma unroll
            for (int p = 0; p < 2; p++) {
                const int k = bk_r + p * 8;
                float4 wv = ld4(W + (size_t)(k0 + k) * DDIM + col0 + bj);
                *(float4*)&Bs[k][bj] = wv;
            }
        } else {
#pragma unroll
            for (int p = 0; p < 2; p++) {
                const int j = lm + p * 64;
                float4 wv = ld4(W + (size_t)(col0 + j) * DDIM + k0 + lk);
                Bs[lk + 0][j] = wv.x;
                Bs[lk + 1][j] = wv.y;
                Bs[lk + 2][j] = wv.z;
                Bs[lk + 3][j] = wv.w;
            }
        }
        __syncthreads();

#pragma unroll
        for (int kk = 0; kk < BK; kk++) {
            float4 a0 = *(const float4*)&As[kk][ty * 4];
            float4 a1 = *(const float4*)&As[kk][64 + ty * 4];
            float4 b0 = *(const float4*)&Bs[kk][tx * 4];
            float4 b1 = *(const float4*)&Bs[kk][64 + tx * 4];
            float ar[8] = {a0.x, a0.y, a0.z, a0.w, a1.x, a1.y, a1.z, a1.w};
            float br[8] = {b0.x, b0.y, b0.z, b0.w, b1.x, b1.y, b1.z, b1.w};
#pragma unroll
            for (int i = 0; i < 8; i++)
#pragma unroll
                for (int j = 0; j < 8; j++)
                    acc[i][j] = fmaf(ar[i], br[j], acc[i][j]);
        }
        __syncthreads();
    }

    // ---- epilogue ----
#pragma unroll
    for (int i = 0; i < 8; i++) {
        const int r = row0 + ty * 4 + (i & 3) + (i >> 2) * 64;
#pragma unroll
        for (int jg = 0; jg < 2; jg++) {
            const int c = col0 + tx * 4 + jg * 64;
            const size_t off = (size_t)r * DDIM + c;
            float av[4];
            av[0] = acc[i][jg * 4 + 0];
            av[1] = acc[i][jg * 4 + 1];
            av[2] = acc[i][jg * 4 + 2];
            av[3] = acc[i][jg * 4 + 3];

            if (MODE == MODE_SP) {
                float bv[4]; *(float4*)bv = ld4(bias + c);
                float ov[4];
#pragma unroll
                for (int q = 0; q < 4; q++) ov[q] = sp_f(av[q] + bv[q]);
                *(float4*)(O1 + off) = *(float4*)ov;
            } else if (MODE == MODE_GV) {
                float bv[4]; *(float4*)bv = ld4(bias + c);
                float ov[4];
#pragma unroll
                for (int q = 0; q < 4; q++) {
                    float s = sp_f(av[q] + bv[q]);
                    ov[q] = 0.5f * expm1f(-s) / s;
                }
                *(float4*)(O1 + off) = *(float4*)ov;
            } else if (MODE == MODE_ZC) {
                float zv[4], sv[4], vv[4];
                *(float4*)zv = ld4(X1 + off);
                *(float4*)sv = ld4(X2 + off);
                *(float4*)vv = ld4(X3 + off);
                float bf[4], zn[4];
#pragma unroll
                for (int q = 0; q < 4; q++) {
                    float svh = sv[q] * vv[q];
                    bf[q] = HG * (svh + 2.0f * av[q]);
                    zn[q] = zv[q] + bf[q] + HG * svh;
                }
                *(float4*)(O1 + off) = *(float4*)bf;
                *(float4*)(O2 + off) = *(float4*)zn;
            } else if (MODE == MODE_FXZ) {
                float bv[4], znv[4], bfv[4], vv[4];
                *(float4*)bv  = ld4(bias + c);
                *(float4*)znv = ld4(X1 + off);
                *(float4*)bfv = ld4(X2 + off);
                *(float4*)vv  = ld4(X3 + off);
                float ov[4];
#pragma unroll
                for (int q = 0; q < 4; q++) {
                    float s = sp_f(av[q] + bv[q]);
                    ov[q] = znv[q] + bfv[q] + HG * s * vv[q];
                }
                *(float4*)(O1 + off) = *(float4*)ov;
            } else {  // MODE_FXV
                float vb[4]; *(float4*)vb = ld4(X3 + off);
                float ov[4];
#pragma unroll
                for (int q = 0; q < 4; q++) ov[q] = vb[q] - HG * av[q];
                *(float4*)(O1 + off) = *(float4*)ov;
            }
        }
    }
}

// ---------------- host driver ----------------------------------------------
extern "C" void kernel_launch(void* const* d_in, const int* in_sizes, int n_in,
                              void* d_out, int out_size)
{
    const float* z0   = (const float*)d_in[0];
    const float* v0   = (const float*)d_in[1];
    const float* W    = (const float*)d_in[2];
    const float* bias = (const float*)d_in[3];

    static float *SZ = nullptr, *BUF, *V, *VH0, *VH1, *TMP, *ZP[3];
    if (!SZ) {
        cudaGetSymbolAddress((void**)&SZ,    gSZ);
        cudaGetSymbolAddress((void**)&BUF,   gBUF);
        cudaGetSymbolAddress((void**)&V,     gV);
        cudaGetSymbolAddress((void**)&VH0,   gVH0);
        cudaGetSymbolAddress((void**)&VH1,   gVH1);
        cudaGetSymbolAddress((void**)&TMP,   gTMP);
        cudaGetSymbolAddress((void**)&ZP[0], gZ0);
        cudaGetSymbolAddress((void**)&ZP[1], gZ1);
        cudaGetSymbolAddress((void**)&ZP[2], gZ2);
    }

    const dim3 grid(DDIM / BN, MBATCH / BM);
    const dim3 blk(256);

    // s(z0)
    rhmc_gemm<MODE_SP, false><<<grid, blk>>>(z0, W, bias, nullptr, nullptr, nullptr, SZ, nullptr);

    const float* zcur = z0;
    const float* vcur = v0;
    int cur = -1;

    for (int l = 0; l < 6; l++) {
        const int a = (cur < 0) ? 0 : (cur + 1) % 3;
        const int b = (cur < 0) ? 1 : (cur + 2) % 3;

        // ---- fx_v: 8 accumulating iterations  vh <- vh - HG*dHdz(z, vh) ----
        float* vping[2] = {VH0, VH1};
        const float* vh = vcur;
        for (int i = 0; i < 8; i++) {
            float* vo = vping[i & 1];
            rhmc_gemm<MODE_FXV, true><<<grid, blk>>>(nullptr, W, bias, SZ, vh, vh, vo, nullptr);
            vh = vo;
        }
        // vh == VH1 after 8 iterations

        // ---- Gv(vh) = 0.5*expm1(-s_vh)/s_vh ----
        rhmc_gemm<MODE_GV, false><<<grid, blk>>>(vh, W, bias, nullptr, nullptr, nullptr, TMP, nullptr);

        // ---- C = Gv@W^T ; BUF = HG*(s_z*vh + 2C) ; zn_1 = z + BUF + HG*s_z*vh ----
        rhmc_gemm<MODE_ZC, true><<<grid, blk>>>(TMP, W, bias, zcur, SZ, vh, BUF, ZP[a]);

        // ---- fx_z: 7 more accumulating iterations  zn <- zn + BUF + HG*s(zn)*vh ----
        const float* zn = ZP[a];
        float* zping[2] = {ZP[b], ZP[a]};
        for (int i = 0; i < 7; i++) {
            float* zo = zping[i & 1];
            rhmc_gemm<MODE_FXZ, false><<<grid, blk>>>(zn, W, bias, zn, BUF, vh, zo, nullptr);
            zn = zo;
        }
        // zn == ZP[b] after 7 iterations (1 + 7 = 8 total applications)

        // ---- s(z_new) (shared with next leapfrog step) ----
        rhmc_gemm<MODE_SP, false><<<grid, blk>>>(zn, W, bias, nullptr, nullptr, nullptr, SZ, nullptr);

        // ---- v_new = vh - HG*dHdz(z_new, vh) ----
        rhmc_gemm<MODE_FXV, true><<<grid, blk>>>(nullptr, W, bias, SZ, vh, vh, V, nullptr);

        zcur = zn;
        vcur = V;
        cur  = b;
    }

    cudaMemcpyAsync(d_out, zcur, (size_t)NELEM * sizeof(float), cudaMemcpyDeviceToDevice);
    cudaMemcpyAsync((float*)d_out + NELEM, vcur, (size_t)NELEM * sizeof(float),
                    cudaMemcpyDeviceToDevice);
}

// round 3
// speedup vs baseline: 1.1663x; 1.1663x over previous
#include <cuda_runtime.h>
#include <math.h>
#include <stdint.h>

#define MBATCH 16384
#define DDIM   256
#define NELEM  (MBATCH * DDIM)

constexpr float HG = 0.005f;   // gamma / 2

constexpr int BM = 128, BN = 128, BK = 32;

enum { MODE_SP = 0, MODE_GV = 1, MODE_ZC = 2, MODE_FXZ = 3, MODE_FXV = 4 };

// ---------------- scratch (static device arrays; no runtime alloc) --------
__device__ float gSZ [NELEM];
__device__ float gBUF[NELEM];
__device__ float gV  [NELEM];
__device__ float gVH0[NELEM];
__device__ float gVH1[NELEM];
__device__ float gTMP[NELEM];
__device__ float gZ0 [NELEM];
__device__ float gZ1 [NELEM];
__device__ float gZ2 [NELEM];

// ---------------- math helpers --------------------------------------------
__device__ __forceinline__ float sp_f(float x) {
    // softplus(x) = max(x,0) + log1p(exp(-|x|))   (matches jax.nn.softplus)
    return fmaxf(x, 0.0f) + log1pf(expf(-fabsf(x)));
}

// dH_dz = G @ W^T with G = 0.5*expm1(-s)*(1/s - vh^2)
__device__ __forceinline__ float gfun(float s, float vh) {
    float e = expm1f(-s);
    return 0.5f * e * (1.0f / s - vh * vh);
}

__device__ __forceinline__ float4 ld4(const float* p) { return *(const float4*)p; }

__device__ __forceinline__ uint32_t to_tf32(float f) {
    uint32_t r;
    asm("cvt.rna.tf32.f32 %0, %1;" : "=r"(r) : "f"(f));
    return r;
}

__device__ __forceinline__ void mma_tf32(float c[4], const uint32_t a[4], const uint32_t b[2]) {
    asm volatile(
        "mma.sync.aligned.m16n8k8.row.col.f32.tf32.tf32.f32 "
        "{%0,%1,%2,%3}, {%4,%5,%6,%7}, {%8,%9}, {%0,%1,%2,%3};"
        : "+f"(c[0]), "+f"(c[1]), "+f"(c[2]), "+f"(c[3])
        : "r"(a[0]), "r"(a[1]), "r"(a[2]), "r"(a[3]), "r"(b[0]), "r"(b[1]));
}

// ---------------- fused epilogue (per float2) -------------------------------
template <int MODE>
__device__ __forceinline__ void epi2(size_t off, int c, float a0, float a1,
                                     const float* __restrict__ bias,
                                     const float* __restrict__ X1,
                                     const float* __restrict__ X2,
                                     const float* __restrict__ X3,
                                     float* __restrict__ O1, float* __restrict__ O2)
{
    if (MODE == MODE_SP) {
        float2 b = *(const float2*)(bias + c);
        float2 o = make_float2(sp_f(a0 + b.x), sp_f(a1 + b.y));
        *(float2*)(O1 + off) = o;
    } else if (MODE == MODE_GV) {
        float2 b = *(const float2*)(bias + c);
        float s0 = sp_f(a0 + b.x), s1 = sp_f(a1 + b.y);
        float2 o = make_float2(0.5f * expm1f(-s0) / s0, 0.5f * expm1f(-s1) / s1);
        *(float2*)(O1 + off) = o;
    } else if (MODE == MODE_ZC) {
        float2 z = *(const float2*)(X1 + off);
        float2 s = *(const float2*)(X2 + off);
        float2 v = *(const float2*)(X3 + off);
        float svh0 = s.x * v.x, svh1 = s.y * v.y;
        float2 bf = make_float2(HG * (svh0 + 2.0f * a0), HG * (svh1 + 2.0f * a1));
        float2 zn = make_float2(z.x + bf.x + HG * svh0, z.y + bf.y + HG * svh1);
        *(float2*)(O1 + off) = bf;
        *(float2*)(O2 + off) = zn;
    } else if (MODE == MODE_FXZ) {
        float2 b  = *(const float2*)(bias + c);
        float2 zn = *(const float2*)(X1 + off);
        float2 bf = *(const float2*)(X2 + off);
        float2 v  = *(const float2*)(X3 + off);
        float s0 = sp_f(a0 + b.x), s1 = sp_f(a1 + b.y);
        float2 o = make_float2(zn.x + bf.x + HG * s0 * v.x, zn.y + bf.y + HG * s1 * v.y);
        *(float2*)(O1 + off) = o;
    } else {  // MODE_FXV
        float2 vb = *(const float2*)(X3 + off);
        float2 o = make_float2(vb.x - HG * a0, vb.y - HG * a1);
        *(float2*)(O1 + off) = o;
    }
}

// ---------------- fused TF32 tensor-core GEMM -------------------------------
// TRANSB=false: acc[r,j] = sum_k A[r,k] * W[k,j]
// TRANSB=true : acc[r,j] = sum_k A[r,k] * W[j,k]
// Modes as in the driver comments. MODE_FXV generates A = gfun(X1,X2) on the fly.
template <int MODE, bool TRANSB>
__global__ __launch_bounds__(256, 2)
void rhmc_gemm(const float* __restrict__ A, const float* __restrict__ W,
               const float* __restrict__ bias,
               const float* __restrict__ X1, const float* __restrict__ X2,
               const float* __restrict__ X3,
               float* __restrict__ O1, float* __restrict__ O2)
{
    // mma-fragment-layout staging buffers (tf32 bits)
    // Af[ks(4)][mtile(8)][lane(32)*4 + reg(4)]   = 4096 u32 = 16KB
    // Bf[ks(4)][ntile(16)][lane(32)*2 + reg(2)]  = 4096 u32 = 16KB
    __shared__ uint32_t Af[4 * 8 * 128];
    __shared__ uint32_t Bf[4 * 16 * 64];

    const int row0 = blockIdx.y * BM;
    const int col0 = blockIdx.x * BN;
    const int tid  = threadIdx.x;
    const int wid  = tid >> 5;
    const int lane = tid & 31;
    const int warp_m = wid >> 2;   // 0..1  (64 rows each)
    const int warp_n = wid & 3;    // 0..3  (32 cols each)

    float acc[4][4][4];
#pragma unroll
    for (int i = 0; i < 4; i++)
#pragma unroll
        for (int j = 0; j < 4; j++)
#pragma unroll
            for (int q = 0; q < 4; q++) acc[i][j][q] = 0.0f;

    for (int k0 = 0; k0 < DDIM; k0 += BK) {
        // ---- stage A chunk (BM x BK) into fragment layout ----
#pragma unroll
        for (int i = 0; i < 4; i++) {
            const int idx = tid + 256 * i;        // 0..1023
            const int m   = idx >> 3;             // 0..127
            const int k   = (idx & 7) << 2;       // 0..28
            const size_t g = (size_t)(row0 + m) * DDIM + k0 + k;
            float4 av;
            if (MODE == MODE_FXV) {
                float4 s4 = ld4(X1 + g);
                float4 v4 = ld4(X2 + g);
                av.x = gfun(s4.x, v4.x);
                av.y = gfun(s4.y, v4.y);
                av.z = gfun(s4.z, v4.z);
                av.w = gfun(s4.w, v4.w);
            } else {
                av = ld4(A + g);
            }
            uint32_t bs[4] = {to_tf32(av.x), to_tf32(av.y), to_tf32(av.z), to_tf32(av.w)};
#pragma unroll
            for (int c = 0; c < 4; c++) {
                const int kk = k + c;
                const int fi = ((kk >> 3) * 8 + (m >> 4)) * 128
                             + ((((m & 7) << 2) | (kk & 3)) << 2)
                             + (((kk >> 2) & 1) << 1) + ((m >> 3) & 1);
                Af[fi] = bs[c];
            }
        }
        // ---- stage B chunk (BK x BN) into fragment layout ----
        if (!TRANSB) {
#pragma unroll
            for (int i = 0; i < 4; i++) {
                const int idx = tid + 256 * i;
                const int k   = idx >> 5;          // 0..31
                const int n   = (idx & 31) << 2;   // 0..124
                float4 wv = ld4(W + (size_t)(k0 + k) * DDIM + col0 + n);
                uint32_t bs[4] = {to_tf32(wv.x), to_tf32(wv.y), to_tf32(wv.z), to_tf32(wv.w)};
#pragma unroll
                for (int c = 0; c < 4; c++) {
                    const int nn = n + c;
                    const int fi = ((k >> 3) * 16 + (nn >> 3)) * 64
                                 + ((((nn & 7) << 2) | (k & 3)) << 1)
                                 + ((k >> 2) & 1);
                    Bf[fi] = bs[c];
                }
            }
        } else {
#pragma unroll
            for (int i = 0; i < 4; i++) {
                const int idx = tid + 256 * i;
                const int n   = idx >> 3;          // 0..127
                const int k   = (idx & 7) << 2;    // 0..28
                float4 wv = ld4(W + (size_t)(col0 + n) * DDIM + k0 + k);
                uint32_t bs[4] = {to_tf32(wv.x), to_tf32(wv.y), to_tf32(wv.z), to_tf32(wv.w)};
#pragma unroll
                for (int c = 0; c < 4; c++) {
                    const int kk = k + c;
                    const int fi = ((kk >> 3) * 16 + (n >> 3)) * 64
                                 + ((((n & 7) << 2) | (kk & 3)) << 1)
                                 + ((kk >> 2) & 1);
                    Bf[fi] = bs[c];
                }
            }
        }
        __syncthreads();

        // ---- tensor-core mainloop over this chunk ----
#pragma unroll
        for (int ks = 0; ks < 4; ks++) {
            uint32_t af[4][4];
            uint32_t bf[4][2];
#pragma unroll
            for (int mt = 0; mt < 4; mt++) {
                const uint32_t* p = &Af[(ks * 8 + warp_m * 4 + mt) * 128 + (lane << 2)];
                uint4 v = *(const uint4*)p;
                af[mt][0] = v.x; af[mt][1] = v.y; af[mt][2] = v.z; af[mt][3] = v.w;
            }
#pragma unroll
            for (int nt = 0; nt < 4; nt++) {
                const uint32_t* p = &Bf[(ks * 16 + warp_n * 4 + nt) * 64 + (lane << 1)];
                uint2 v = *(const uint2*)p;
                bf[nt][0] = v.x; bf[nt][1] = v.y;
            }
#pragma unroll
            for (int mt = 0; mt < 4; mt++)
#pragma unroll
                for (int nt = 0; nt < 4; nt++)
                    mma_tf32(acc[mt][nt], af[mt], bf[nt]);
        }
        __syncthreads();
    }

    // ---- fused epilogue ----
#pragma unroll
    for (int mt = 0; mt < 4; mt++) {
#pragma unroll
        for (int nt = 0; nt < 4; nt++) {
            const int r = row0 + warp_m * 64 + mt * 16 + (lane >> 2);
            const int c = col0 + warp_n * 32 + nt * 8 + ((lane & 3) << 1);
            const size_t off0 = (size_t)r * DDIM + c;
            const size_t off1 = off0 + (size_t)8 * DDIM;
            epi2<MODE>(off0, c, acc[mt][nt][0], acc[mt][nt][1], bias, X1, X2, X3, O1, O2);
            epi2<MODE>(off1, c, acc[mt][nt][2], acc[mt][nt][3], bias, X1, X2, X3, O1, O2);
        }
    }
}

// ---------------- host driver ----------------------------------------------
extern "C" void kernel_launch(void* const* d_in, const int* in_sizes, int n_in,
                              void* d_out, int out_size)
{
    const float* z0   = (const float*)d_in[0];
    const float* v0   = (const float*)d_in[1];
    const float* W    = (const float*)d_in[2];
    const float* bias = (const float*)d_in[3];

    static float *SZ = nullptr, *BUF, *V, *VH0, *VH1, *TMP, *ZP[3];
    if (!SZ) {
        cudaGetSymbolAddress((void**)&SZ,    gSZ);
        cudaGetSymbolAddress((void**)&BUF,   gBUF);
        cudaGetSymbolAddress((void**)&V,     gV);
        cudaGetSymbolAddress((void**)&VH0,   gVH0);
        cudaGetSymbolAddress((void**)&VH1,   gVH1);
        cudaGetSymbolAddress((void**)&TMP,   gTMP);
        cudaGetSymbolAddress((void**)&ZP[0], gZ0);
        cudaGetSymbolAddress((void**)&ZP[1], gZ1);
        cudaGetSymbolAddress((void**)&ZP[2], gZ2);
    }

    const dim3 grid(DDIM / BN, MBATCH / BM);
    const dim3 blk(256);

    // s(z0)
    rhmc_gemm<MODE_SP, false><<<grid, blk>>>(z0, W, bias, nullptr, nullptr, nullptr, SZ, nullptr);

    const float* zcur = z0;
    const float* vcur = v0;
    int cur = -1;

    for (int l = 0; l < 6; l++) {
        const int a = (cur < 0) ? 0 : (cur + 1) % 3;
        const int b = (cur < 0) ? 1 : (cur + 2) % 3;

        // ---- fx_v: 8 accumulating iterations  vh <- vh - HG*dHdz(z, vh) ----
        float* vping[2] = {VH0, VH1};
        const float* vh = vcur;
        for (int i = 0; i < 8; i++) {
            float* vo = vping[i & 1];
            rhmc_gemm<MODE_FXV, true><<<grid, blk>>>(nullptr, W, bias, SZ, vh, vh, vo, nullptr);
            vh = vo;
        }
        // vh == VH1 after 8 iterations

        // ---- Gv(vh) = 0.5*expm1(-s_vh)/s_vh ----
        rhmc_gemm<MODE_GV, false><<<grid, blk>>>(vh, W, bias, nullptr, nullptr, nullptr, TMP, nullptr);

        // ---- C = Gv@W^T ; BUF = HG*(s_z*vh + 2C) ; zn_1 = z + BUF + HG*s_z*vh ----
        rhmc_gemm<MODE_ZC, true><<<grid, blk>>>(TMP, W, bias, zcur, SZ, vh, BUF, ZP[a]);

        // ---- fx_z: 7 more accumulating iterations  zn <- zn + BUF + HG*s(zn)*vh ----
        const float* zn = ZP[a];
        float* zping[2] = {ZP[b], ZP[a]};
        for (int i = 0; i < 7; i++) {
            float* zo = zping[i & 1];
            rhmc_gemm<MODE_FXZ, false><<<grid, blk>>>(zn, W, bias, zn, BUF, vh, zo, nullptr);
            zn = zo;
        }
        // zn == ZP[b] after 7 iterations (1 + 7 = 8 total applications)

        // ---- s(z_new) (shared with next leapfrog step) ----
        rhmc_gemm<MODE_SP, false><<<grid, blk>>>(zn, W, bias, nullptr, nullptr, nullptr, SZ, nullptr);

        // ---- v_new = vh - HG*dHdz(z_new, vh) ----
        rhmc_gemm<MODE_FXV, true><<<grid, blk>>>(nullptr, W, bias, SZ, vh, vh, V, nullptr);

        zcur = zn;
        vcur = V;
        cur  = b;
    }

    cudaMemcpyAsync(d_out, zcur, (size_t)NELEM * sizeof(float), cudaMemcpyDeviceToDevice);
    cudaMemcpyAsync((float*)d_out + NELEM, vcur, (size_t)NELEM * sizeof(float),
                    cudaMemcpyDeviceToDevice);
}

// round 5
// speedup vs baseline: 1.9763x; 1.6945x over previous
#include <cuda_runtime.h>
#include <math.h>
#include <stdint.h>

#define MBATCH 16384
#define DDIM   256
#define NELEM  (MBATCH * DDIM)

constexpr float HG = 0.005f;   // gamma / 2

constexpr int BM = 128, BN = 128, BK = 64;
constexpr int ASTRIDE = 68;    // 68 % 32 == 4  -> conflict-free direct frag lds
constexpr int SMEM_BYTES = 2 * BM * ASTRIDE * (int)sizeof(float);   // 69632

enum { MODE_SP = 0, MODE_GV = 1, MODE_ZC = 2, MODE_FXZ = 3, MODE_FXV = 4 };

// ---------------- scratch (static device arrays; no runtime alloc) --------
__device__ float gSZ [NELEM];
__device__ float gBUF[NELEM];
__device__ float gV  [NELEM];
__device__ float gVH0[NELEM];
__device__ float gVH1[NELEM];
__device__ float gTMP[NELEM];
__device__ float gZ0 [NELEM];
__device__ float gZ1 [NELEM];
__device__ float gZ2 [NELEM];

// Precomputed tf32 W fragments (mma-fragment order), 256KB each.
// layout: idx = ((kt*32 + nt)*32 + lane)*2 + reg
//   kt = k>>3 (0..31), nt = n>>3 (0..31)
//   n = nt*8 + (lane>>2),  k = kt*8 + (lane&3) + 4*reg
__device__ uint32_t gWN[65536];   // B[k][n] = W[k][n]      (A @ W)
__device__ uint32_t gWT[65536];   // B[k][n] = W[n][k]      (A @ W^T)

// ---------------- math helpers --------------------------------------------
__device__ __forceinline__ float sp_f(float x) {
    return fmaxf(x, 0.0f) + log1pf(expf(-fabsf(x)));   // jax softplus
}
__device__ __forceinline__ float gfun(float s, float vh) {
    float e = expm1f(-s);
    return 0.5f * e * (1.0f / s - vh * vh);
}
__device__ __forceinline__ float4 ld4(const float* p) { return *(const float4*)p; }

__device__ __forceinline__ uint32_t to_tf32(float f) {
    uint32_t r;
    asm("cvt.rna.tf32.f32 %0, %1;" : "=r"(r) : "f"(f));
    return r;
}

__device__ __forceinline__ void mma_tf32(float c[4], const uint32_t a[4], const uint32_t b[2]) {
    asm volatile(
        "mma.sync.aligned.m16n8k8.row.col.f32.tf32.tf32.f32 "
        "{%0,%1,%2,%3}, {%4,%5,%6,%7}, {%8,%9}, {%0,%1,%2,%3};"
        : "+f"(c[0]), "+f"(c[1]), "+f"(c[2]), "+f"(c[3])
        : "r"(a[0]), "r"(a[1]), "r"(a[2]), "r"(a[3]), "r"(b[0]), "r"(b[1]));
}

__device__ __forceinline__ void cp16(float* smem_dst, const float* gsrc) {
    uint32_t s = (uint32_t)__cvta_generic_to_shared(smem_dst);
    asm volatile("cp.async.cg.shared.global [%0], [%1], 16;" :: "r"(s), "l"(gsrc));
}
__device__ __forceinline__ void cp_commit() { asm volatile("cp.async.commit_group;"); }
template <int N>
__device__ __forceinline__ void cp_wait() { asm volatile("cp.async.wait_group %0;" :: "n"(N)); }

// ---------------- W fragment precompute -------------------------------------
__global__ void prep_wfrags(const float* __restrict__ W) {
    int idx = blockIdx.x * 256 + threadIdx.x;   // 0..65535
    int reg  = idx & 1;
    int lane = (idx >> 1) & 31;
    int nt   = (idx >> 6) & 31;
    int kt   = idx >> 11;
    int n = nt * 8 + (lane >> 2);
    int k = kt * 8 + (lane & 3) + 4 * reg;
    gWN[idx] = to_tf32(W[k * DDIM + n]);
    gWT[idx] = to_tf32(W[n * DDIM + k]);
}

// ---------------- fused epilogue (per float2) -------------------------------
template <int MODE>
__device__ __forceinline__ void epi2(size_t off, int c, float a0, float a1,
                                     const float* __restrict__ bias,
                                     const float* __restrict__ X1,
                                     const float* __restrict__ X2,
                                     const float* __restrict__ X3,
                                     float* __restrict__ O1, float* __restrict__ O2)
{
    if (MODE == MODE_SP) {
        float2 b = *(const float2*)(bias + c);
        float2 o = make_float2(sp_f(a0 + b.x), sp_f(a1 + b.y));
        *(float2*)(O1 + off) = o;
    } else if (MODE == MODE_GV) {
        float2 b = *(const float2*)(bias + c);
        float s0 = sp_f(a0 + b.x), s1 = sp_f(a1 + b.y);
        float2 o = make_float2(0.5f * expm1f(-s0) / s0, 0.5f * expm1f(-s1) / s1);
        *(float2*)(O1 + off) = o;
    } else if (MODE == MODE_ZC) {
        float2 z = *(const float2*)(X1 + off);
        float2 s = *(const float2*)(X2 + off);
        float2 v = *(const float2*)(X3 + off);
        float svh0 = s.x * v.x, svh1 = s.y * v.y;
        float2 bf = make_float2(HG * (svh0 + 2.0f * a0), HG * (svh1 + 2.0f * a1));
        float2 zn = make_float2(z.x + bf.x + HG * svh0, z.y + bf.y + HG * svh1);
        *(float2*)(O1 + off) = bf;
        *(float2*)(O2 + off) = zn;
    } else if (MODE == MODE_FXZ) {
        float2 b  = *(const float2*)(bias + c);
        float2 zn = *(const float2*)(X1 + off);
        float2 bf = *(const float2*)(X2 + off);
        float2 v  = *(const float2*)(X3 + off);
        float s0 = sp_f(a0 + b.x), s1 = sp_f(a1 + b.y);
        float2 o = make_float2(zn.x + bf.x + HG * s0 * v.x, zn.y + bf.y + HG * s1 * v.y);
        *(float2*)(O1 + off) = o;
    } else {  // MODE_FXV
        float2 vb = *(const float2*)(X3 + off);
        float2 o = make_float2(vb.x - HG * a0, vb.y - HG * a1);
        *(float2*)(O1 + off) = o;
    }
}

// ---------------- fused TF32 tensor-core GEMM -------------------------------
template <int MODE, bool TRANSB>
__global__ __launch_bounds__(256, 2)
void rhmc_gemm(const float* __restrict__ A, const float* __restrict__ bias,
               const float* __restrict__ X1, const float* __restrict__ X2,
               const float* __restrict__ X3,
               float* __restrict__ O1, float* __restrict__ O2)
{
    extern __shared__ float Asm[];                 // 2 x BM x ASTRIDE
    float* Abuf[2] = {Asm, Asm + BM * ASTRIDE};

    const uint32_t* __restrict__ Wf = TRANSB ? gWT : gWN;

    const int row0 = blockIdx.y * BM;
    const int col0 = blockIdx.x * BN;
    const int tid  = threadIdx.x;
    const int lane = tid & 31;
    const int wid  = tid >> 5;
    const int warp_m = wid >> 2;   // 0..1  (64 rows)
    const int warp_n = wid & 3;    // 0..3  (32 cols)

    float acc[4][4][4];
#pragma unroll
    for (int i = 0; i < 4; i++)
#pragma unroll
        for (int j = 0; j < 4; j++)
#pragma unroll
            for (int q = 0; q < 4; q++) acc[i][j][q] = 0.0f;

    // ---- chunk copy: A[row0..row0+127][c*64 .. c*64+63] -> Abuf[buf] ----
    auto copyA = [&](int buf, int c) {
#pragma unroll
        for (int i = 0; i < 8; i++) {
            const int idx = i * 256 + tid;         // 0..2047
            const int m   = idx >> 4;              // 0..127
            const int o   = (idx & 15) * 4;        // 0..60
            const size_t g = (size_t)(row0 + m) * DDIM + c * BK + o;
            float* dst = &Abuf[buf][m * ASTRIDE + o];
            if (MODE == MODE_FXV) {
                float4 s4 = ld4(X1 + g);
                float4 v4 = ld4(X2 + g);
                float4 av;
                av.x = gfun(s4.x, v4.x);
                av.y = gfun(s4.y, v4.y);
                av.z = gfun(s4.z, v4.z);
                av.w = gfun(s4.w, v4.w);
                *(float4*)dst = av;
            } else {
                cp16(dst, A + g);
            }
        }
    };

    copyA(0, 0);
    cp_commit();

#pragma unroll
    for (int c = 0; c < 4; c++) {
        if (c < 3) { copyA((c + 1) & 1, c + 1); cp_commit(); }
        if (c < 3) cp_wait<1>(); else cp_wait<0>();
        __syncthreads();

        const float* Ab = Abuf[c & 1];
#pragma unroll
        for (int ktl = 0; ktl < 8; ktl++) {
            const int kt = c * 8 + ktl;
            // B fragments: direct ldg from precomputed frags
            uint32_t bf[4][2];
#pragma unroll
            for (int nt = 0; nt < 4; nt++) {
                const int ntg = (col0 >> 3) + warp_n * 4 + nt;
                const uint2* p = (const uint2*)(Wf + (((size_t)kt * 32 + ntg) * 32 + lane) * 2);
                uint2 v = __ldg(p);
                bf[nt][0] = v.x; bf[nt][1] = v.y;
            }
            const int kk = ktl * 8 + (lane & 3);
#pragma unroll
            for (int mt = 0; mt < 4; mt++) {
                const int r = warp_m * 64 + mt * 16 + (lane >> 2);
                uint32_t af[4];
                af[0] = __float_as_uint(Ab[r * ASTRIDE + kk]);
                af[1] = __float_as_uint(Ab[(r + 8) * ASTRIDE + kk]);
                af[2] = __float_as_uint(Ab[r * ASTRIDE + kk + 4]);
                af[3] = __float_as_uint(Ab[(r + 8) * ASTRIDE + kk + 4]);
#pragma unroll
                for (int nt = 0; nt < 4; nt++)
                    mma_tf32(acc[mt][nt], af, bf[nt]);
            }
        }
        __syncthreads();
    }

    // ---- fused epilogue ----
#pragma unroll
    for (int mt = 0; mt < 4; mt++) {
#pragma unroll
        for (int nt = 0; nt < 4; nt++) {
            const int r = row0 + warp_m * 64 + mt * 16 + (lane >> 2);
            const int c = col0 + warp_n * 32 + nt * 8 + ((lane & 3) << 1);
            const size_t off0 = (size_t)r * DDIM + c;
            const size_t off1 = off0 + (size_t)8 * DDIM;
            epi2<MODE>(off0, c, acc[mt][nt][0], acc[mt][nt][1], bias, X1, X2, X3, O1, O2);
            epi2<MODE>(off1, c, acc[mt][nt][2], acc[mt][nt][3], bias, X1, X2, X3, O1, O2);
        }
    }
}

// ---------------- host driver ----------------------------------------------
static void set_smem_caps() {
    cudaFuncSetAttribute(rhmc_gemm<MODE_SP,  false>, cudaFuncAttributeMaxDynamicSharedMemorySize, SMEM_BYTES);
    cudaFuncSetAttribute(rhmc_gemm<MODE_GV,  false>, cudaFuncAttributeMaxDynamicSharedMemorySize, SMEM_BYTES);
    cudaFuncSetAttribute(rhmc_gemm<MODE_ZC,  true >, cudaFuncAttributeMaxDynamicSharedMemorySize, SMEM_BYTES);
    cudaFuncSetAttribute(rhmc_gemm<MODE_FXZ, false>, cudaFuncAttributeMaxDynamicSharedMemorySize, SMEM_BYTES);
    cudaFuncSetAttribute(rhmc_gemm<MODE_FXV, true >, cudaFuncAttributeMaxDynamicSharedMemorySize, SMEM_BYTES);
}

extern "C" void kernel_launch(void* const* d_in, const int* in_sizes, int n_in,
                              void* d_out, int out_size)
{
    const float* z0   = (const float*)d_in[0];
    const float* v0   = (const float*)d_in[1];
    const float* W    = (const float*)d_in[2];
    const float* bias = (const float*)d_in[3];

    set_smem_caps();

    static float *SZ = nullptr, *BUF, *V, *VH0, *VH1, *TMP, *ZP[3];
    if (!SZ) {
        cudaGetSymbolAddress((void**)&SZ,    gSZ);
        cudaGetSymbolAddress((void**)&BUF,   gBUF);
        cudaGetSymbolAddress((void**)&V,     gV);
        cudaGetSymbolAddress((void**)&VH0,   gVH0);
        cudaGetSymbolAddress((void**)&VH1,   gVH1);
        cudaGetSymbolAddress((void**)&TMP,   gTMP);
        cudaGetSymbolAddress((void**)&ZP[0], gZ0);
        cudaGetSymbolAddress((void**)&ZP[1], gZ1);
        cudaGetSymbolAddress((void**)&ZP[2], gZ2);
    }

    const dim3 grid(DDIM / BN, MBATCH / BM);
    const dim3 blk(256);

    prep_wfrags<<<256, 256>>>(W);

    // s(z0)
    rhmc_gemm<MODE_SP, false><<<grid, blk, SMEM_BYTES>>>(z0, bias, nullptr, nullptr, nullptr, SZ, nullptr);

    const float* zcur = z0;
    const float* vcur = v0;
    int cur = -1;

    for (int l = 0; l < 6; l++) {
        const int a = (cur < 0) ? 0 : (cur + 1) % 3;
        const int b = (cur < 0) ? 1 : (cur + 2) % 3;

        // ---- fx_v: 8 accumulating iterations  vh <- vh - HG*dHdz(z, vh) ----
        float* vping[2] = {VH0, VH1};
        const float* vh = vcur;
        for (int i = 0; i < 8; i++) {
            float* vo = vping[i & 1];
            rhmc_gemm<MODE_FXV, true><<<grid, blk, SMEM_BYTES>>>(nullptr, bias, SZ, vh, vh, vo, nullptr);
            vh = vo;
        }
        // vh == VH1 after 8 iterations

        // ---- Gv(vh) = 0.5*expm1(-s_vh)/s_vh ----
        rhmc_gemm<MODE_GV, false><<<grid, blk, SMEM_BYTES>>>(vh, bias, nullptr, nullptr, nullptr, TMP, nullptr);

        // ---- C = Gv@W^T ; BUF = HG*(s_z*vh + 2C) ; zn_1 = z + BUF + HG*s_z*vh ----
        rhmc_gemm<MODE_ZC, true><<<grid, blk, SMEM_BYTES>>>(TMP, bias, zcur, SZ, vh, BUF, ZP[a]);

        // ---- fx_z: 7 more accumulating iterations  zn <- zn + BUF + HG*s(zn)*vh ----
        const float* zn = ZP[a];
        float* zping[2] = {ZP[b], ZP[a]};
        for (int i = 0; i < 7; i++) {
            float* zo = zping[i & 1];
            rhmc_gemm<MODE_FXZ, false><<<grid, blk, SMEM_BYTES>>>(zn, bias, zn, BUF, vh, zo, nullptr);
            zn = zo;
        }
        // zn == ZP[b] after 7 iterations (1 + 7 = 8 total applications)

        // ---- s(z_new) (shared with next leapfrog step) ----
        rhmc_gemm<MODE_SP, false><<<grid, blk, SMEM_BYTES>>>(zn, bias, nullptr, nullptr, nullptr, SZ, nullptr);

        // ---- v_new = vh - HG*dHdz(z_new, vh) ----
        rhmc_gemm<MODE_FXV, true><<<grid, blk, SMEM_BYTES>>>(nullptr, bias, SZ, vh, vh, V, nullptr);

        zcur = zn;
        vcur = V;
        cur  = b;
    }

    cudaMemcpyAsync(d_out, zcur, (size_t)NELEM * sizeof(float), cudaMemcpyDeviceToDevice);
    cudaMemcpyAsync((float*)d_out + NELEM, vcur, (size_t)NELEM * sizeof(float),
                    cudaMemcpyDeviceToDevice);
}

// round 6
// speedup vs baseline: 2.4206x; 1.2248x over previous
#include <cuda_runtime.h>
#include <math.h>
#include <stdint.h>

#define MBATCH 16384
#define DDIM   256
#define NELEM  (MBATCH * DDIM)

constexpr float HG = 0.005f;   // gamma / 2

constexpr int BM = 128, BN = 128, BK = 64;
constexpr int ASTRIDE = 68;    // 68 % 32 == 4  -> conflict-free direct frag lds
constexpr int SMEM_BYTES = 2 * BM * ASTRIDE * (int)sizeof(float);   // 69632

enum { MODE_SP = 0, MODE_GV = 1, MODE_ZC = 2, MODE_FXZ = 3, MODE_FXV = 4, MODE_RW = 5 };

// ---------------- scratch (static device arrays; no runtime alloc) --------
__device__ float gSZ [NELEM];
__device__ float gE  [NELEM];
__device__ float gR  [NELEM];
__device__ float gHGR[NELEM];
__device__ float gBUF[NELEM];
__device__ float gV  [NELEM];
__device__ float gVH0[NELEM];
__device__ float gVH1[NELEM];
__device__ float gTMP[NELEM];
__device__ float gZ0 [NELEM];
__device__ float gZ1 [NELEM];
__device__ float gZ2 [NELEM];

// Precomputed tf32 W fragments (mma-fragment order), 256KB each.
__device__ uint32_t gWN[65536];   // B[k][n] = W[k][n]      (A @ W)
__device__ uint32_t gWT[65536];   // B[k][n] = W[n][k]      (A @ W^T)

// ---------------- math helpers --------------------------------------------
__device__ __forceinline__ float sp_f(float x) {          // precise softplus
    return fmaxf(x, 0.0f) + log1pf(expf(-fabsf(x)));
}
__device__ __forceinline__ float sp_fast(float x) {       // MUFU softplus
    return fmaxf(x, 0.0f) + __logf(1.0f + __expf(-fabsf(x)));
}
__device__ __forceinline__ float4 ld4(const float* p) { return *(const float4*)p; }

__device__ __forceinline__ uint32_t to_tf32(float f) {
    uint32_t r;
    asm("cvt.rna.tf32.f32 %0, %1;" : "=r"(r) : "f"(f));
    return r;
}

__device__ __forceinline__ void mma_tf32(float c[4], const uint32_t a[4], const uint32_t b[2]) {
    asm volatile(
        "mma.sync.aligned.m16n8k8.row.col.f32.tf32.tf32.f32 "
        "{%0,%1,%2,%3}, {%4,%5,%6,%7}, {%8,%9}, {%0,%1,%2,%3};"
        : "+f"(c[0]), "+f"(c[1]), "+f"(c[2]), "+f"(c[3])
        : "r"(a[0]), "r"(a[1]), "r"(a[2]), "r"(a[3]), "r"(b[0]), "r"(b[1]));
}

__device__ __forceinline__ void cp16(float* smem_dst, const float* gsrc) {
    uint32_t s = (uint32_t)__cvta_generic_to_shared(smem_dst);
    asm volatile("cp.async.cg.shared.global [%0], [%1], 16;" :: "r"(s), "l"(gsrc));
}
__device__ __forceinline__ void cp_commit() { asm volatile("cp.async.commit_group;"); }
template <int N>
__device__ __forceinline__ void cp_wait() { asm volatile("cp.async.wait_group %0;" :: "n"(N)); }

// ---------------- W fragment precompute -------------------------------------
__global__ void prep_wfrags(const float* __restrict__ W) {
    int idx = blockIdx.x * 256 + threadIdx.x;   // 0..65535
    int reg  = idx & 1;
    int lane = (idx >> 1) & 31;
    int nt   = (idx >> 6) & 31;
    int kt   = idx >> 11;
    int n = nt * 8 + (lane >> 2);
    int k = kt * 8 + (lane & 3) + 4 * reg;
    gWN[idx] = to_tf32(W[k * DDIM + n]);
    gWT[idx] = to_tf32(W[n * DDIM + k]);
}

// ---------------- fused epilogue (per float2) -------------------------------
// SP : s = softplus(acc+bias); O1=s, O2=e=0.5*expm1(-s), O3=r=e/s
// GV : O1 = 0.5*expm1(-s)/s
// ZC : O1 = BUF = HG*(SZ*vh + 2*acc); O2 = z + BUF + HG*SZ*vh   (X1=z,X2=SZ,X3=vh)
// FXZ: s = sp_fast(acc+bias); O1 = X1 + X2 + HG*s*X3            (X1=zn,X2=BUF,X3=vh)
// FXV: O1 = X3 - X4 + HG*acc                                    (X3=vh, X4=HGR)
// RW : O1 = HG*acc
template <int MODE>
__device__ __forceinline__ void epi2(size_t off, int c, float a0, float a1,
                                     const float* __restrict__ bias,
                                     const float* __restrict__ X1,
                                     const float* __restrict__ X2,
                                     const float* __restrict__ X3,
                                     const float* __restrict__ X4,
                                     float* __restrict__ O1, float* __restrict__ O2,
                                     float* __restrict__ O3)
{
    if (MODE == MODE_SP) {
        float2 b = *(const float2*)(bias + c);
        float s0 = sp_f(a0 + b.x), s1 = sp_f(a1 + b.y);
        float e0 = 0.5f * expm1f(-s0), e1 = 0.5f * expm1f(-s1);
        *(float2*)(O1 + off) = make_float2(s0, s1);
        *(float2*)(O2 + off) = make_float2(e0, e1);
        *(float2*)(O3 + off) = make_float2(__fdividef(e0, s0), __fdividef(e1, s1));
    } else if (MODE == MODE_GV) {
        float2 b = *(const float2*)(bias + c);
        float s0 = sp_f(a0 + b.x), s1 = sp_f(a1 + b.y);
        float2 o = make_float2(__fdividef(0.5f * expm1f(-s0), s0),
                               __fdividef(0.5f * expm1f(-s1), s1));
        *(float2*)(O1 + off) = o;
    } else if (MODE == MODE_ZC) {
        float2 z = *(const float2*)(X1 + off);
        float2 s = *(const float2*)(X2 + off);
        float2 v = *(const float2*)(X3 + off);
        float svh0 = s.x * v.x, svh1 = s.y * v.y;
        float2 bf = make_float2(HG * (svh0 + 2.0f * a0), HG * (svh1 + 2.0f * a1));
        float2 zn = make_float2(z.x + bf.x + HG * svh0, z.y + bf.y + HG * svh1);
        *(float2*)(O1 + off) = bf;
        *(float2*)(O2 + off) = zn;
    } else if (MODE == MODE_FXZ) {
        float2 b  = *(const float2*)(bias + c);
        float2 zn = *(const float2*)(X1 + off);
        float2 bf = *(const float2*)(X2 + off);
        float2 v  = *(const float2*)(X3 + off);
        float s0 = sp_fast(a0 + b.x), s1 = sp_fast(a1 + b.y);
        float2 o = make_float2(zn.x + bf.x + HG * s0 * v.x, zn.y + bf.y + HG * s1 * v.y);
        *(float2*)(O1 + off) = o;
    } else if (MODE == MODE_FXV) {
        float2 vb  = *(const float2*)(X3 + off);
        float2 hgr = *(const float2*)(X4 + off);
        float2 o = make_float2(vb.x - hgr.x + HG * a0, vb.y - hgr.y + HG * a1);
        *(float2*)(O1 + off) = o;
    } else {  // MODE_RW
        *(float2*)(O1 + off) = make_float2(HG * a0, HG * a1);
    }
}

// ---------------- fused TF32 tensor-core GEMM -------------------------------
// MODE_FXV stages A = X1 * X2 * X2 (= e * vh^2) on the fly; others cp.async A.
template <int MODE, bool TRANSB>
__global__ __launch_bounds__(256, 2)
void rhmc_gemm(const float* __restrict__ A, const float* __restrict__ bias,
               const float* __restrict__ X1, const float* __restrict__ X2,
               const float* __restrict__ X3, const float* __restrict__ X4,
               float* __restrict__ O1, float* __restrict__ O2,
               float* __restrict__ O3)
{
    extern __shared__ float Asm[];                 // 2 x BM x ASTRIDE
    float* Abuf[2] = {Asm, Asm + BM * ASTRIDE};

    const uint32_t* __restrict__ Wf = TRANSB ? gWT : gWN;

    const int row0 = blockIdx.y * BM;
    const int col0 = blockIdx.x * BN;
    const int tid  = threadIdx.x;
    const int lane = tid & 31;
    const int wid  = tid >> 5;
    const int warp_m = wid >> 2;   // 0..1  (64 rows)
    const int warp_n = wid & 3;    // 0..3  (32 cols)

    float acc[4][4][4];
#pragma unroll
    for (int i = 0; i < 4; i++)
#pragma unroll
        for (int j = 0; j < 4; j++)
#pragma unroll
            for (int q = 0; q < 4; q++) acc[i][j][q] = 0.0f;

    auto copyA = [&](int buf, int c) {
#pragma unroll
        for (int i = 0; i < 8; i++) {
            const int idx = i * 256 + tid;         // 0..2047
            const int m   = idx >> 4;              // 0..127
            const int o   = (idx & 15) * 4;        // 0..60
            const size_t g = (size_t)(row0 + m) * DDIM + c * BK + o;
            float* dst = &Abuf[buf][m * ASTRIDE + o];
            if (MODE == MODE_FXV) {
                float4 e4 = ld4(X1 + g);
                float4 v4 = ld4(X2 + g);
                float4 av;
                av.x = e4.x * v4.x * v4.x;
                av.y = e4.y * v4.y * v4.y;
                av.z = e4.z * v4.z * v4.z;
                av.w = e4.w * v4.w * v4.w;
                *(float4*)dst = av;
            } else {
                cp16(dst, A + g);
            }
        }
    };

    copyA(0, 0);
    cp_commit();

#pragma unroll
    for (int c = 0; c < 4; c++) {
        if (c < 3) { copyA((c + 1) & 1, c + 1); cp_commit(); }
        if (c < 3) cp_wait<1>(); else cp_wait<0>();
        __syncthreads();

        const float* Ab = Abuf[c & 1];
#pragma unroll
        for (int ktl = 0; ktl < 8; ktl++) {
            const int kt = c * 8 + ktl;
            uint32_t bf[4][2];
#pragma unroll
            for (int nt = 0; nt < 4; nt++) {
                const int ntg = (col0 >> 3) + warp_n * 4 + nt;
                const uint2* p = (const uint2*)(Wf + (((size_t)kt * 32 + ntg) * 32 + lane) * 2);
                uint2 v = __ldg(p);
                bf[nt][0] = v.x; bf[nt][1] = v.y;
            }
            const int kk = ktl * 8 + (lane & 3);
#pragma unroll
            for (int mt = 0; mt < 4; mt++) {
                const int r = warp_m * 64 + mt * 16 + (lane >> 2);
                uint32_t af[4];
                af[0] = __float_as_uint(Ab[r * ASTRIDE + kk]);
                af[1] = __float_as_uint(Ab[(r + 8) * ASTRIDE + kk]);
                af[2] = __float_as_uint(Ab[r * ASTRIDE + kk + 4]);
                af[3] = __float_as_uint(Ab[(r + 8) * ASTRIDE + kk + 4]);
#pragma unroll
                for (int nt = 0; nt < 4; nt++)
                    mma_tf32(acc[mt][nt], af, bf[nt]);
            }
        }
        __syncthreads();
    }

#pragma unroll
    for (int mt = 0; mt < 4; mt++) {
#pragma unroll
        for (int nt = 0; nt < 4; nt++) {
            const int r = row0 + warp_m * 64 + mt * 16 + (lane >> 2);
            const int c = col0 + warp_n * 32 + nt * 8 + ((lane & 3) << 1);
            const size_t off0 = (size_t)r * DDIM + c;
            const size_t off1 = off0 + (size_t)8 * DDIM;
            epi2<MODE>(off0, c, acc[mt][nt][0], acc[mt][nt][1], bias, X1, X2, X3, X4, O1, O2, O3);
            epi2<MODE>(off1, c, acc[mt][nt][2], acc[mt][nt][3], bias, X1, X2, X3, X4, O1, O2, O3);
        }
    }
}

// ---------------- host driver ----------------------------------------------
static void set_smem_caps() {
    cudaFuncSetAttribute(rhmc_gemm<MODE_SP,  false>, cudaFuncAttributeMaxDynamicSharedMemorySize, SMEM_BYTES);
    cudaFuncSetAttribute(rhmc_gemm<MODE_GV,  false>, cudaFuncAttributeMaxDynamicSharedMemorySize, SMEM_BYTES);
    cudaFuncSetAttribute(rhmc_gemm<MODE_ZC,  true >, cudaFuncAttributeMaxDynamicSharedMemorySize, SMEM_BYTES);
    cudaFuncSetAttribute(rhmc_gemm<MODE_FXZ, false>, cudaFuncAttributeMaxDynamicSharedMemorySize, SMEM_BYTES);
    cudaFuncSetAttribute(rhmc_gemm<MODE_FXV, true >, cudaFuncAttributeMaxDynamicSharedMemorySize, SMEM_BYTES);
    cudaFuncSetAttribute(rhmc_gemm<MODE_RW,  true >, cudaFuncAttributeMaxDynamicSharedMemorySize, SMEM_BYTES);
}

extern "C" void kernel_launch(void* const* d_in, const int* in_sizes, int n_in,
                              void* d_out, int out_size)
{
    const float* z0   = (const float*)d_in[0];
    const float* v0   = (const float*)d_in[1];
    const float* W    = (const float*)d_in[2];
    const float* bias = (const float*)d_in[3];

    set_smem_caps();

    static float *SZ = nullptr, *E, *RR, *HGR, *BUF, *V, *VH0, *VH1, *TMP, *ZP[3];
    if (!SZ) {
        cudaGetSymbolAddress((void**)&SZ,    gSZ);
        cudaGetSymbolAddress((void**)&E,     gE);
        cudaGetSymbolAddress((void**)&RR,    gR);
        cudaGetSymbolAddress((void**)&HGR,   gHGR);
        cudaGetSymbolAddress((void**)&BUF,   gBUF);
        cudaGetSymbolAddress((void**)&V,     gV);
        cudaGetSymbolAddress((void**)&VH0,   gVH0);
        cudaGetSymbolAddress((void**)&VH1,   gVH1);
        cudaGetSymbolAddress((void**)&TMP,   gTMP);
        cudaGetSymbolAddress((void**)&ZP[0], gZ0);
        cudaGetSymbolAddress((void**)&ZP[1], gZ1);
        cudaGetSymbolAddress((void**)&ZP[2], gZ2);
    }

    const dim3 grid(DDIM / BN, MBATCH / BM);
    const dim3 blk(256);

    prep_wfrags<<<256, 256>>>(W);

    // s(z0), e(z0), r(z0)
    rhmc_gemm<MODE_SP, false><<<grid, blk, SMEM_BYTES>>>(z0, bias, nullptr, nullptr, nullptr, nullptr, SZ, E, RR);
    // HGR = HG * (r @ W^T)
    rhmc_gemm<MODE_RW, true ><<<grid, blk, SMEM_BYTES>>>(RR, bias, nullptr, nullptr, nullptr, nullptr, HGR, nullptr, nullptr);

    const float* zcur = z0;
    const float* vcur = v0;
    int cur = -1;

    for (int l = 0; l < 6; l++) {
        const int a = (cur < 0) ? 0 : (cur + 1) % 3;
        const int b = (cur < 0) ? 1 : (cur + 2) % 3;

        // ---- fx_v: 8 iterations  vh <- vh - HGR + HG*((e*vh^2) @ W^T) ----
        float* vping[2] = {VH0, VH1};
        const float* vh = vcur;
        for (int i = 0; i < 8; i++) {
            float* vo = vping[i & 1];
            rhmc_gemm<MODE_FXV, true><<<grid, blk, SMEM_BYTES>>>(nullptr, bias, E, vh, vh, HGR, vo, nullptr, nullptr);
            vh = vo;
        }
        // vh == VH1 after 8 iterations

        // ---- Gv(vh) = 0.5*expm1(-s_vh)/s_vh ----
        rhmc_gemm<MODE_GV, false><<<grid, blk, SMEM_BYTES>>>(vh, bias, nullptr, nullptr, nullptr, nullptr, TMP, nullptr, nullptr);

        // ---- C = Gv@W^T ; BUF = HG*(s_z*vh + 2C) ; zn_1 = z + BUF + HG*s_z*vh ----
        rhmc_gemm<MODE_ZC, true><<<grid, blk, SMEM_BYTES>>>(TMP, bias, zcur, SZ, vh, nullptr, BUF, ZP[a], nullptr);

        // ---- fx_z: 7 more iterations  zn <- zn + BUF + HG*s(zn)*vh ----
        const float* zn = ZP[a];
        float* zping[2] = {ZP[b], ZP[a]};
        for (int i = 0; i < 7; i++) {
            float* zo = zping[i & 1];
            rhmc_gemm<MODE_FXZ, false><<<grid, blk, SMEM_BYTES>>>(zn, bias, zn, BUF, vh, nullptr, zo, nullptr, nullptr);
            zn = zo;
        }
        // zn == ZP[b]  (1 + 7 = 8 total applications)

        // ---- s,e,r of z_new (feeds final v-update AND next leapfrog step) ----
        rhmc_gemm<MODE_SP, false><<<grid, blk, SMEM_BYTES>>>(zn, bias, nullptr, nullptr, nullptr, nullptr, SZ, E, RR);
        rhmc_gemm<MODE_RW, true ><<<grid, blk, SMEM_BYTES>>>(RR, bias, nullptr, nullptr, nullptr, nullptr, HGR, nullptr, nullptr);

        // ---- v_new = vh - HGR_new + HG*((e_new*vh^2) @ W^T) ----
        rhmc_gemm<MODE_FXV, true><<<grid, blk, SMEM_BYTES>>>(nullptr, bias, E, vh, vh, HGR, V, nullptr, nullptr);

        zcur = zn;
        vcur = V;
        cur  = b;
    }

    cudaMemcpyAsync(d_out, zcur, (size_t)NELEM * sizeof(float), cudaMemcpyDeviceToDevice);
    cudaMemcpyAsync((float*)d_out + NELEM, vcur, (size_t)NELEM * sizeof(float),
                    cudaMemcpyDeviceToDevice);
}